// round 10
// baseline (speedup 1.0000x reference)
#include <cuda_runtime.h>
#include <math_constants.h>
#include <cstdint>

#define BB 8192
#define CC 2048
#define NBINS 4096
#define GAMA 0.3f
#define FULLM 0xffffffffu

// ---------------- scratch (static __device__, no allocs) ----------------
__device__ float g_rowmax[BB]; // max over cols [1,C)
__device__ float g_neg[BB];    // sigmoid(max excluding label col and col 0)
__device__ float g_posm[BB];   // m_i = sigmoid(x[i,y])-gamma, +INF invalid
__device__ int   g_notI64;     // 1 = labels int32, 0 = int64

__device__ __forceinline__ float sigmoidf_(float v) { return 1.0f / (1.0f + __expf(-v)); }
// Monotonic bin for v in (0,1): positive-float bits are order-preserving.
__device__ __forceinline__ int binOf(float v) { return (int)(__float_as_uint(v) >> 19); }

__device__ __forceinline__ float max4(float4 v) {
    return fmaxf(fmaxf(v.x, v.y), fmaxf(v.z, v.w));
}

// ---------------- K1: warp-per-row max over cols [1,C); block 1024 detects dtype ----------------
// 16 unconditional front-batched LDG.128 per lane (MLP = 16), fmax tree, warp reduce.
__global__ __launch_bounds__(256) void k_row(const float* __restrict__ x,
                                             const int* __restrict__ wy) {
    const int tid  = threadIdx.x;
    const int lane = tid & 31;
    const int w    = tid >> 5;

    if (blockIdx.x == 1024) {
        // dedicated dtype-detect block: reads only words [0, BB) — safe for both dtypes.
        // int64 labels (<2048) -> odd words are zero high halves.
        int f = 0;
        for (int i = tid; i < BB / 2; i += 256) f |= wy[2 * i + 1];
#pragma unroll
        for (int o = 16; o; o >>= 1) f |= __shfl_xor_sync(FULLM, f, o);
        __shared__ int sf[8];
        if (lane == 0) sf[w] = f;
        __syncthreads();
        if (tid == 0) {
            int r = 0;
#pragma unroll
            for (int k = 0; k < 8; k++) r |= sf[k];
            g_notI64 = (r != 0);
        }
        return;
    }

    const int row = blockIdx.x * 8 + w;
    const float4* xr = (const float4*)(x + (size_t)row * CC);

    // 16 independent loads, fully front-batched
    float4 v[16];
#pragma unroll
    for (int k = 0; k < 16; k++) v[k] = __ldg(xr + lane + 32 * k);
    if (lane == 0) v[0].x = -CUDART_INF_F;   // exclude col 0

    float t[16];
#pragma unroll
    for (int k = 0; k < 16; k++) t[k] = max4(v[k]);
#pragma unroll
    for (int s = 8; s; s >>= 1)
#pragma unroll
        for (int k = 0; k < 16; k++) if (k < s) t[k] = fmaxf(t[k], t[k + s]);
    float mx = t[0];
#pragma unroll
    for (int o = 16; o; o >>= 1) mx = fmaxf(mx, __shfl_xor_sync(FULLM, mx, o));
    if (lane == 0) g_rowmax[row] = mx;
}

// ---------------- K1b: label select + pos gather; rare cooperative rescan ----------------
__global__ __launch_bounds__(256) void k_pos(const float* __restrict__ x,
                                             const int* __restrict__ wy) {
    const int i    = blockIdx.x * 256 + threadIdx.x;   // 32*256 = 8192
    const int lane = threadIdx.x & 31;
    const int notI64 = g_notI64;
    // wy[2*i] only dereferenced when labels proven int64 (buffer has 2*BB words)
    int yq = notI64 ? wy[i] : wy[2 * i];
    float m1 = g_rowmax[i];
    float px = __ldg(&x[(size_t)i * CC + yq]);

    float neg = m1;                       // correct unless label col holds the max
    bool need = (yq != 0) && (px == m1);  // exact: px is an element, m1 the exact max
    unsigned bal = __ballot_sync(FULLM, need);
    while (bal) {                         // ~4 rows expected across the whole grid
        int l  = __ffs(bal) - 1; bal &= bal - 1;
        int ri = __shfl_sync(FULLM, i,  l);
        int ry = __shfl_sync(FULLM, yq, l);
        const float4* xr = (const float4*)(x + (size_t)ri * CC);
        float mm = -CUDART_INF_F;
        for (int c4 = lane; c4 < CC / 4; c4 += 32) {
            float4 v = __ldg(xr + c4);
            int c = c4 * 4;
            if (c == 0)      v.x = -CUDART_INF_F;
            if (c + 0 == ry) v.x = -CUDART_INF_F;
            if (c + 1 == ry) v.y = -CUDART_INF_F;
            if (c + 2 == ry) v.z = -CUDART_INF_F;
            if (c + 3 == ry) v.w = -CUDART_INF_F;
            mm = fmaxf(mm, max4(v));
        }
#pragma unroll
        for (int o = 16; o; o >>= 1) mm = fmaxf(mm, __shfl_xor_sync(FULLM, mm, o));
        if (lane == l) neg = mm;          // exact masked max for this row
    }
    g_neg[i]  = sigmoidf_(neg);
    g_posm[i] = (yq != 0) ? (sigmoidf_(px) - GAMA) : CUDART_INF_F;
}

// ---------------- K2: hist + scan + scatter + suffix + queries (all smem, warp scans) ----------------
// smem layout (bytes from base):
//   [0      , 65544 )  double sS1[8193]   (overlay: float sraw[8192] @0,
//   [65544  , 131088)  double sS2[8193]    int shist[4096] @32768, int scursor[4096] @49152)
//   [131088 , 163856)  float  ssorted[8192]
//   [163856 , 180248)  int    sbinStart[4097] (+pad)
//   [180248 , 188440)  double p1[1024]
//   [188440 , 196632)  double p2[1024]
//   [196632 , 200728)  int    iscan[1024]
#define K2_SMEM 200728

__global__ __launch_bounds__(1024, 1) void k_main(float* __restrict__ out) {
    extern __shared__ unsigned char sm[];
    double* sS1      = (double*)(sm);
    double* sS2      = (double*)(sm + 65544);
    float*  ssorted  = (float*) (sm + 131088);
    int*    sbinStart= (int*)   (sm + 163856);
    double* p1       = (double*)(sm + 180248);
    double* p2       = (double*)(sm + 188440);
    int*    iscan    = (int*)   (sm + 196632);
    float*  sraw     = (float*) (sm);           // overlay, dead before sS1 written
    int*    shist    = (int*)   (sm + 32768);   // overlay
    int*    scursor  = (int*)   (sm + 49152);   // overlay

    const int tid  = threadIdx.x;
    const int lane = tid & 31;
    const int wid  = tid >> 5;

    // ---- phase 1: contiguous loads; neg -> smem, m -> regs ----
    float pm[8];
#pragma unroll
    for (int k = 0; k < 8; k++) {
        int i = tid + k * 1024;
        sraw[i] = g_neg[i];
        pm[k]   = g_posm[i];
    }
    for (int i = tid; i < NBINS; i += 1024) shist[i] = 0;
    __syncthreads();

    // ---- phase 2: histogram (warp-aggregated atomics) ----
#pragma unroll
    for (int k = 0; k < 8; k++) {
        int b = binOf(sraw[tid + k * 1024]);
        unsigned mask = __match_any_sync(FULLM, b);
        if (lane == (__ffs(mask) - 1)) atomicAdd(&shist[b], __popc(mask));
    }
    __syncthreads();

    // ---- phase 3: exclusive scan over 4096 bins (warp-shuffle scan) ----
    const int tb = tid * 4;
    int h0 = shist[tb], h1 = shist[tb + 1], h2 = shist[tb + 2], h3 = shist[tb + 3];
    int tsum = h0 + h1 + h2 + h3;
    int v = tsum;
#pragma unroll
    for (int o = 1; o < 32; o <<= 1) {
        int t = __shfl_up_sync(FULLM, v, o);
        if (lane >= o) v += t;
    }
    if (lane == 31) iscan[wid] = v;             // warp totals
    __syncthreads();
    if (wid == 0) {
        int w = iscan[lane];
        int s = w;
#pragma unroll
        for (int o = 1; o < 32; o <<= 1) {
            int t = __shfl_up_sync(FULLM, s, o);
            if (lane >= o) s += t;
        }
        iscan[32 + lane] = s - w;               // exclusive warp offsets
    }
    __syncthreads();
    {
        int ex = v + iscan[32 + wid] - tsum;    // exclusive prefix for this thread
        sbinStart[tb] = ex;     scursor[tb]     = ex; ex += h0;
        sbinStart[tb + 1] = ex; scursor[tb + 1] = ex; ex += h1;
        sbinStart[tb + 2] = ex; scursor[tb + 2] = ex; ex += h2;
        sbinStart[tb + 3] = ex; scursor[tb + 3] = ex; ex += h3;
        if (tid == 1023) sbinStart[NBINS] = ex; // = BB
    }
    __syncthreads();

    // ---- phase 4: scatter into bin-grouped order (warp-aggregated) ----
#pragma unroll
    for (int k = 0; k < 8; k++) {
        float val = sraw[tid + k * 1024];
        int b = binOf(val);
        unsigned mask = __match_any_sync(FULLM, b);
        int leader = __ffs(mask) - 1;
        int pos0 = 0;
        if (lane == leader) pos0 = atomicAdd(&scursor[b], __popc(mask));
        pos0 = __shfl_sync(FULLM, pos0, leader);
        ssorted[pos0 + __popc(mask & ((1u << lane) - 1u))] = val;
    }
    __syncthreads();   // sraw/shist/scursor dead from here

    // ---- phase 5: element-level suffix sums (double), warp-shuffle suffix scan ----
    const int base8 = tid * 8;
    double tl1[8], tl2[8];
    double a1 = 0.0, a2 = 0.0;
#pragma unroll
    for (int k = 7; k >= 0; --k) {
        float n = ssorted[base8 + k];
        a1 += (double)n;
        a2 += (double)n * (double)n;
        tl1[k] = a1; tl2[k] = a2;
    }
    double s1 = a1, s2 = a2;
#pragma unroll
    for (int o = 1; o < 32; o <<= 1) {
        double t1 = __shfl_down_sync(FULLM, s1, o);
        double t2 = __shfl_down_sync(FULLM, s2, o);
        if (lane + o < 32) { s1 += t1; s2 += t2; }
    }
    if (lane == 0) { p1[wid] = s1; p2[wid] = s2; }  // warp totals
    __syncthreads();
    if (wid == 0) {
        double w1 = p1[lane], w2 = p2[lane];
        double e1 = w1, e2 = w2;
#pragma unroll
        for (int o = 1; o < 32; o <<= 1) {
            double t1 = __shfl_down_sync(FULLM, e1, o);
            double t2 = __shfl_down_sync(FULLM, e2, o);
            if (lane + o < 32) { e1 += t1; e2 += t2; }
        }
        p1[32 + lane] = e1 - w1;               // exclusive suffix of higher warps
        p2[32 + lane] = e2 - w2;
    }
    __syncthreads();
    {
        double o1 = s1 + p1[32 + wid] - a1;    // sum strictly after this thread's chunk
        double o2 = s2 + p2[32 + wid] - a2;
#pragma unroll
        for (int k = 0; k < 8; k++) {
            sS1[base8 + k] = tl1[k] + o1;
            sS2[base8 + k] = tl2[k] + o2;
        }
        if (tid == 0) { sS1[BB] = 0.0; sS2[BB] = 0.0; }
    }
    __syncthreads();

    // ---- phase 6: queries + warp reduction ----
    double acc = 0.0;
    int vc = 0;
#pragma unroll
    for (int k = 0; k < 8; k++) {
        float m = pm[k];
        if (!(m < 1.0f)) continue;       // invalid (+INF)
        vc++;
        long long cnt; double S1, S2;
        if (m <= 0.0f) {
            cnt = BB; S1 = sS1[0]; S2 = sS2[0];
        } else {
            int b = binOf(m); if (b > NBINS - 1) b = NBINS - 1;
            int st = sbinStart[b], en = sbinStart[b + 1];
            cnt = BB - en; S1 = sS1[en]; S2 = sS2[en];
            for (int t = st; t < en; t++) {          // exact boundary-bin scan
                float n = ssorted[t];
                if (n > m) { cnt++; S1 += (double)n; S2 += (double)n * (double)n; }
            }
        }
        double md = (double)m;
        acc += (double)cnt * md * md - 2.0 * md * S1 + S2;
    }
#pragma unroll
    for (int o = 16; o; o >>= 1) {
        acc += __shfl_down_sync(FULLM, acc, o);
        vc  += __shfl_down_sync(FULLM, vc,  o);
    }
    if (lane == 0) { p1[wid] = acc; iscan[wid] = vc; }
    __syncthreads();
    if (tid == 0) {
        double s = 0.0; int c = 0;
#pragma unroll
        for (int w = 0; w < 32; w++) { s += p1[w]; c += iscan[w]; }
        out[0] = (float)(s / ((double)c + 1.0) / ((double)BB + 1.0));
    }
}

// ---------------- launch ----------------
extern "C" void kernel_launch(void* const* d_in, const int* in_sizes, int n_in,
                              void* d_out, int out_size) {
    const float* x = (const float*)d_in[0];
    const int*   y = (const int*)d_in[1];

    k_row<<<1025, 256>>>(x, y);
    k_pos<<<32, 256>>>(x, y);
    cudaFuncSetAttribute(k_main, cudaFuncAttributeMaxDynamicSharedMemorySize, K2_SMEM);
    k_main<<<1, 1024, K2_SMEM>>>((float*)d_out);
}

// round 11
// speedup vs baseline: 1.0350x; 1.0350x over previous
#include <cuda_runtime.h>
#include <math_constants.h>
#include <cstdint>

#define BB 8192
#define CC 2048
#define NBINS 4096
#define GAMA 0.3f
#define FULLM 0xffffffffu

// ---------------- scratch (static __device__, no allocs) ----------------
__device__ float g_rowmax[BB]; // max over cols [1,C)
__device__ float g_neg[BB];    // sigmoid(max excluding label col and col 0)
__device__ float g_posm[BB];   // m_i = sigmoid(x[i,y])-gamma, +INF invalid
__device__ int   g_notI64;     // 1 = labels int32, 0 = int64

__device__ __forceinline__ float sigmoidf_(float v) { return 1.0f / (1.0f + __expf(-v)); }
// Monotonic bin for v in (0,1): positive-float bits are order-preserving.
__device__ __forceinline__ int binOf(float v) { return (int)(__float_as_uint(v) >> 19); }

__device__ __forceinline__ float max4(float4 v) {
    return fmaxf(fmaxf(v.x, v.y), fmaxf(v.z, v.w));
}

// ---------------- K1: two rows per 128-thread block; 8 front-batched LDG.128/thread ----------------
__global__ __launch_bounds__(128) void k_row(const float* __restrict__ x,
                                             const int* __restrict__ wy) {
    const int tid  = threadIdx.x;
    const int lane = tid & 31;

    if (blockIdx.x == BB / 2) {
        // dedicated dtype-detect block: reads only words [0, BB) — safe for both dtypes.
        // int64 labels (<2048) -> odd words are zero high halves.
        int f = 0;
        for (int i = tid; i < BB / 2; i += 128) f |= wy[2 * i + 1];
#pragma unroll
        for (int o = 16; o; o >>= 1) f |= __shfl_xor_sync(FULLM, f, o);
        __shared__ int sf[4];
        if (lane == 0) sf[tid >> 5] = f;
        __syncthreads();
        if (tid == 0) g_notI64 = ((sf[0] | sf[1] | sf[2] | sf[3]) != 0);
        return;
    }

    const int row0 = blockIdx.x * 2;
    const float4* xa = (const float4*)(x + (size_t)row0 * CC);
    const float4* xb = (const float4*)(x + (size_t)(row0 + 1) * CC);

    // 8 independent loads (4 per row), front-batched
    float4 a0 = __ldg(xa + tid);
    float4 a1 = __ldg(xa + tid + 128);
    float4 a2 = __ldg(xa + tid + 256);
    float4 a3 = __ldg(xa + tid + 384);
    float4 b0 = __ldg(xb + tid);
    float4 b1 = __ldg(xb + tid + 128);
    float4 b2 = __ldg(xb + tid + 256);
    float4 b3 = __ldg(xb + tid + 384);

    if (tid == 0) { a0.x = -CUDART_INF_F; b0.x = -CUDART_INF_F; }  // exclude col 0

    float ma = fmaxf(fmaxf(max4(a0), max4(a1)), fmaxf(max4(a2), max4(a3)));
    float mb = fmaxf(fmaxf(max4(b0), max4(b1)), fmaxf(max4(b2), max4(b3)));
#pragma unroll
    for (int o = 16; o; o >>= 1) {
        ma = fmaxf(ma, __shfl_xor_sync(FULLM, ma, o));
        mb = fmaxf(mb, __shfl_xor_sync(FULLM, mb, o));
    }
    __shared__ float wa[4], wb[4];
    if (lane == 0) { int w = tid >> 5; wa[w] = ma; wb[w] = mb; }
    __syncthreads();
    if (tid == 0) {
        float ra = fmaxf(fmaxf(wa[0], wa[1]), fmaxf(wa[2], wa[3]));
        float rb = fmaxf(fmaxf(wb[0], wb[1]), fmaxf(wb[2], wb[3]));
        *(float2*)&g_rowmax[row0] = make_float2(ra, rb);   // row0 even -> 8B aligned
    }
}

// ---------------- K1b: label select + pos gather; rare cooperative rescan ----------------
__global__ __launch_bounds__(256) void k_pos(const float* __restrict__ x,
                                             const int* __restrict__ wy) {
    const int i    = blockIdx.x * 256 + threadIdx.x;   // 32*256 = 8192
    const int lane = threadIdx.x & 31;
    const int notI64 = g_notI64;
    // wy[2*i] only dereferenced when labels proven int64 (buffer has 2*BB words)
    int yq = notI64 ? wy[i] : wy[2 * i];
    float m1 = g_rowmax[i];
    float px = __ldg(&x[(size_t)i * CC + yq]);

    float neg = m1;                       // correct unless label col holds the max
    bool need = (yq != 0) && (px == m1);  // exact: px is an element, m1 the exact max
    unsigned bal = __ballot_sync(FULLM, need);
    while (bal) {                         // ~4 rows expected across the whole grid
        int l  = __ffs(bal) - 1; bal &= bal - 1;
        int ri = __shfl_sync(FULLM, i,  l);
        int ry = __shfl_sync(FULLM, yq, l);
        const float4* xr = (const float4*)(x + (size_t)ri * CC);
        float mm = -CUDART_INF_F;
        for (int c4 = lane; c4 < CC / 4; c4 += 32) {
            float4 v = __ldg(xr + c4);
            int c = c4 * 4;
            if (c == 0)      v.x = -CUDART_INF_F;
            if (c + 0 == ry) v.x = -CUDART_INF_F;
            if (c + 1 == ry) v.y = -CUDART_INF_F;
            if (c + 2 == ry) v.z = -CUDART_INF_F;
            if (c + 3 == ry) v.w = -CUDART_INF_F;
            mm = fmaxf(mm, max4(v));
        }
#pragma unroll
        for (int o = 16; o; o >>= 1) mm = fmaxf(mm, __shfl_xor_sync(FULLM, mm, o));
        if (lane == l) neg = mm;          // exact masked max for this row
    }
    g_neg[i]  = sigmoidf_(neg);
    g_posm[i] = (yq != 0) ? (sigmoidf_(px) - GAMA) : CUDART_INF_F;
}

// ---------------- K2: hist + scan + scatter + suffix + queries (all smem, warp scans) ----------------
// smem layout (bytes from base):
//   [0      , 65544 )  double sS1[8193]   (overlay: float sraw[8192] @0,
//   [65544  , 131088)  double sS2[8193]    int shist[4096] @32768, int scursor[4096] @49152)
//   [131088 , 163856)  float  ssorted[8192]
//   [163856 , 180248)  int    sbinStart[4097] (+pad)
//   [180248 , 188440)  double p1[1024]
//   [188440 , 196632)  double p2[1024]
//   [196632 , 200728)  int    iscan[1024]
#define K2_SMEM 200728

__global__ __launch_bounds__(1024, 1) void k_main(float* __restrict__ out) {
    extern __shared__ unsigned char sm[];
    double* sS1      = (double*)(sm);
    double* sS2      = (double*)(sm + 65544);
    float*  ssorted  = (float*) (sm + 131088);
    int*    sbinStart= (int*)   (sm + 163856);
    double* p1       = (double*)(sm + 180248);
    double* p2       = (double*)(sm + 188440);
    int*    iscan    = (int*)   (sm + 196632);
    float*  sraw     = (float*) (sm);           // overlay, dead before sS1 written
    int*    shist    = (int*)   (sm + 32768);   // overlay
    int*    scursor  = (int*)   (sm + 49152);   // overlay

    const int tid  = threadIdx.x;
    const int lane = tid & 31;
    const int wid  = tid >> 5;

    // ---- phase 1: contiguous loads; neg -> smem, m -> regs ----
    float pm[8];
#pragma unroll
    for (int k = 0; k < 8; k++) {
        int i = tid + k * 1024;
        sraw[i] = g_neg[i];
        pm[k]   = g_posm[i];
    }
    for (int i = tid; i < NBINS; i += 1024) shist[i] = 0;
    __syncthreads();

    // ---- phase 2: histogram (warp-aggregated atomics) ----
#pragma unroll
    for (int k = 0; k < 8; k++) {
        int b = binOf(sraw[tid + k * 1024]);
        unsigned mask = __match_any_sync(FULLM, b);
        if (lane == (__ffs(mask) - 1)) atomicAdd(&shist[b], __popc(mask));
    }
    __syncthreads();

    // ---- phase 3: exclusive scan over 4096 bins (warp-shuffle scan) ----
    const int tb = tid * 4;
    int h0 = shist[tb], h1 = shist[tb + 1], h2 = shist[tb + 2], h3 = shist[tb + 3];
    int tsum = h0 + h1 + h2 + h3;
    int v = tsum;
#pragma unroll
    for (int o = 1; o < 32; o <<= 1) {
        int t = __shfl_up_sync(FULLM, v, o);
        if (lane >= o) v += t;
    }
    if (lane == 31) iscan[wid] = v;             // warp totals
    __syncthreads();
    if (wid == 0) {
        int w = iscan[lane];
        int s = w;
#pragma unroll
        for (int o = 1; o < 32; o <<= 1) {
            int t = __shfl_up_sync(FULLM, s, o);
            if (lane >= o) s += t;
        }
        iscan[32 + lane] = s - w;               // exclusive warp offsets
    }
    __syncthreads();
    {
        int ex = v + iscan[32 + wid] - tsum;    // exclusive prefix for this thread
        sbinStart[tb] = ex;     scursor[tb]     = ex; ex += h0;
        sbinStart[tb + 1] = ex; scursor[tb + 1] = ex; ex += h1;
        sbinStart[tb + 2] = ex; scursor[tb + 2] = ex; ex += h2;
        sbinStart[tb + 3] = ex; scursor[tb + 3] = ex; ex += h3;
        if (tid == 1023) sbinStart[NBINS] = ex; // = BB
    }
    __syncthreads();

    // ---- phase 4: scatter into bin-grouped order (warp-aggregated) ----
#pragma unroll
    for (int k = 0; k < 8; k++) {
        float val = sraw[tid + k * 1024];
        int b = binOf(val);
        unsigned mask = __match_any_sync(FULLM, b);
        int leader = __ffs(mask) - 1;
        int pos0 = 0;
        if (lane == leader) pos0 = atomicAdd(&scursor[b], __popc(mask));
        pos0 = __shfl_sync(FULLM, pos0, leader);
        ssorted[pos0 + __popc(mask & ((1u << lane) - 1u))] = val;
    }
    __syncthreads();   // sraw/shist/scursor dead from here

    // ---- phase 5: element-level suffix sums (double), warp-shuffle suffix scan ----
    const int base8 = tid * 8;
    double tl1[8], tl2[8];
    double a1 = 0.0, a2 = 0.0;
#pragma unroll
    for (int k = 7; k >= 0; --k) {
        float n = ssorted[base8 + k];
        a1 += (double)n;
        a2 += (double)n * (double)n;
        tl1[k] = a1; tl2[k] = a2;
    }
    double s1 = a1, s2 = a2;
#pragma unroll
    for (int o = 1; o < 32; o <<= 1) {
        double t1 = __shfl_down_sync(FULLM, s1, o);
        double t2 = __shfl_down_sync(FULLM, s2, o);
        if (lane + o < 32) { s1 += t1; s2 += t2; }
    }
    if (lane == 0) { p1[wid] = s1; p2[wid] = s2; }  // warp totals
    __syncthreads();
    if (wid == 0) {
        double w1 = p1[lane], w2 = p2[lane];
        double e1 = w1, e2 = w2;
#pragma unroll
        for (int o = 1; o < 32; o <<= 1) {
            double t1 = __shfl_down_sync(FULLM, e1, o);
            double t2 = __shfl_down_sync(FULLM, e2, o);
            if (lane + o < 32) { e1 += t1; e2 += t2; }
        }
        p1[32 + lane] = e1 - w1;               // exclusive suffix of higher warps
        p2[32 + lane] = e2 - w2;
    }
    __syncthreads();
    {
        double o1 = s1 + p1[32 + wid] - a1;    // sum strictly after this thread's chunk
        double o2 = s2 + p2[32 + wid] - a2;
#pragma unroll
        for (int k = 0; k < 8; k++) {
            sS1[base8 + k] = tl1[k] + o1;
            sS2[base8 + k] = tl2[k] + o2;
        }
        if (tid == 0) { sS1[BB] = 0.0; sS2[BB] = 0.0; }
    }
    __syncthreads();

    // ---- phase 6: queries + warp reduction ----
    double acc = 0.0;
    int vc = 0;
#pragma unroll
    for (int k = 0; k < 8; k++) {
        float m = pm[k];
        if (!(m < 1.0f)) continue;       // invalid (+INF)
        vc++;
        long long cnt; double S1, S2;
        if (m <= 0.0f) {
            cnt = BB; S1 = sS1[0]; S2 = sS2[0];
        } else {
            int b = binOf(m); if (b > NBINS - 1) b = NBINS - 1;
            int st = sbinStart[b], en = sbinStart[b + 1];
            cnt = BB - en; S1 = sS1[en]; S2 = sS2[en];
            for (int t = st; t < en; t++) {          // exact boundary-bin scan
                float n = ssorted[t];
                if (n > m) { cnt++; S1 += (double)n; S2 += (double)n * (double)n; }
            }
        }
        double md = (double)m;
        acc += (double)cnt * md * md - 2.0 * md * S1 + S2;
    }
#pragma unroll
    for (int o = 16; o; o >>= 1) {
        acc += __shfl_down_sync(FULLM, acc, o);
        vc  += __shfl_down_sync(FULLM, vc,  o);
    }
    if (lane == 0) { p1[wid] = acc; iscan[wid] = vc; }
    __syncthreads();
    if (tid == 0) {
        double s = 0.0; int c = 0;
#pragma unroll
        for (int w = 0; w < 32; w++) { s += p1[w]; c += iscan[w]; }
        out[0] = (float)(s / ((double)c + 1.0) / ((double)BB + 1.0));
    }
}

// ---------------- launch ----------------
extern "C" void kernel_launch(void* const* d_in, const int* in_sizes, int n_in,
                              void* d_out, int out_size) {
    const float* x = (const float*)d_in[0];
    const int*   y = (const int*)d_in[1];

    k_row<<<BB / 2 + 1, 128>>>(x, y);
    k_pos<<<32, 256>>>(x, y);
    cudaFuncSetAttribute(k_main, cudaFuncAttributeMaxDynamicSharedMemorySize, K2_SMEM);
    k_main<<<1, 1024, K2_SMEM>>>((float*)d_out);
}

// round 12
// speedup vs baseline: 1.0816x; 1.0450x over previous
#include <cuda_runtime.h>
#include <math_constants.h>
#include <cstdint>

#define BB 8192
#define CC 2048
#define NBINS 4096
#define GAMA 0.3f
#define FULLM 0xffffffffu

// ---------------- scratch (static __device__, no allocs) ----------------
__device__ float g_rowmax[BB]; // max over cols [1,C)
__device__ float g_neg[BB];    // sigmoid(max excluding label col and col 0)
__device__ float g_posm[BB];   // m_i = sigmoid(x[i,y])-gamma, +INF invalid
__device__ int   g_notI64;     // 1 = labels int32, 0 = int64

__device__ __forceinline__ float sigmoidf_(float v) { return 1.0f / (1.0f + __expf(-v)); }
// Monotonic bin for v in (0,1): positive-float bits are order-preserving.
__device__ __forceinline__ int binOf(float v) { return (int)(__float_as_uint(v) >> 19); }

__device__ __forceinline__ float max4(float4 v) {
    return fmaxf(fmaxf(v.x, v.y), fmaxf(v.z, v.w));
}

// forced non-sinkable vector load: keeps all results live, emits consecutive LDG.128
#define LDG128(dst, ptr)                                                        \
    asm volatile("ld.global.nc.v4.f32 {%0,%1,%2,%3}, [%4];"                     \
                 : "=f"(dst.x), "=f"(dst.y), "=f"(dst.z), "=f"(dst.w)           \
                 : "l"(ptr))

// ---------------- K1: two rows per 128-thread block; 8 asm-batched LDG.128/thread ----------------
__global__ __launch_bounds__(128) void k_row(const float* __restrict__ x,
                                             const int* __restrict__ wy) {
    const int tid  = threadIdx.x;
    const int lane = tid & 31;

    if (blockIdx.x == BB / 2) {
        // dedicated dtype-detect block: reads only words [0, BB) — safe for both dtypes.
        // int64 labels (<2048) -> odd words are zero high halves.
        int f = 0;
        for (int i = tid; i < BB / 2; i += 128) f |= wy[2 * i + 1];
#pragma unroll
        for (int o = 16; o; o >>= 1) f |= __shfl_xor_sync(FULLM, f, o);
        __shared__ int sf[4];
        if (lane == 0) sf[tid >> 5] = f;
        __syncthreads();
        if (tid == 0) g_notI64 = ((sf[0] | sf[1] | sf[2] | sf[3]) != 0);
        return;
    }

    const int row0 = blockIdx.x * 2;
    const float4* xa = (const float4*)(x + (size_t)row0 * CC);
    const float4* xb = (const float4*)(x + (size_t)(row0 + 1) * CC);

    // 8 consecutive LDG.128, results all live (MLP_p1 = 8)
    float4 a0, a1, a2, a3, b0, b1, b2, b3;
    LDG128(a0, xa + tid);
    LDG128(a1, xa + tid + 128);
    LDG128(a2, xa + tid + 256);
    LDG128(a3, xa + tid + 384);
    LDG128(b0, xb + tid);
    LDG128(b1, xb + tid + 128);
    LDG128(b2, xb + tid + 256);
    LDG128(b3, xb + tid + 384);

    if (tid == 0) { a0.x = -CUDART_INF_F; b0.x = -CUDART_INF_F; }  // exclude col 0

    float ma = fmaxf(fmaxf(max4(a0), max4(a1)), fmaxf(max4(a2), max4(a3)));
    float mb = fmaxf(fmaxf(max4(b0), max4(b1)), fmaxf(max4(b2), max4(b3)));
#pragma unroll
    for (int o = 16; o; o >>= 1) {
        ma = fmaxf(ma, __shfl_xor_sync(FULLM, ma, o));
        mb = fmaxf(mb, __shfl_xor_sync(FULLM, mb, o));
    }
    __shared__ float wa[4], wb[4];
    if (lane == 0) { int w = tid >> 5; wa[w] = ma; wb[w] = mb; }
    __syncthreads();
    if (tid == 0) {
        float ra = fmaxf(fmaxf(wa[0], wa[1]), fmaxf(wa[2], wa[3]));
        float rb = fmaxf(fmaxf(wb[0], wb[1]), fmaxf(wb[2], wb[3]));
        *(float2*)&g_rowmax[row0] = make_float2(ra, rb);   // row0 even -> 8B aligned
    }
}

// ---------------- K1b: label select + pos gather; rare cooperative rescan ----------------
__global__ __launch_bounds__(128) void k_pos(const float* __restrict__ x,
                                             const int* __restrict__ wy) {
    const int i    = blockIdx.x * 128 + threadIdx.x;   // 64*128 = 8192
    const int lane = threadIdx.x & 31;
    const int notI64 = g_notI64;
    // wy[2*i] only dereferenced when labels proven int64 (buffer has 2*BB words)
    int yq = notI64 ? wy[i] : wy[2 * i];
    float m1 = g_rowmax[i];
    float px = __ldg(&x[(size_t)i * CC + yq]);

    float neg = m1;                       // correct unless label col holds the max
    bool need = (yq != 0) && (px == m1);  // exact: px is an element, m1 the exact max
    unsigned bal = __ballot_sync(FULLM, need);
    while (bal) {                         // ~4 rows expected across the whole grid
        int l  = __ffs(bal) - 1; bal &= bal - 1;
        int ri = __shfl_sync(FULLM, i,  l);
        int ry = __shfl_sync(FULLM, yq, l);
        const float4* xr = (const float4*)(x + (size_t)ri * CC);
        float mm = -CUDART_INF_F;
        for (int c4 = lane; c4 < CC / 4; c4 += 32) {
            float4 v = __ldg(xr + c4);
            int c = c4 * 4;
            if (c == 0)      v.x = -CUDART_INF_F;
            if (c + 0 == ry) v.x = -CUDART_INF_F;
            if (c + 1 == ry) v.y = -CUDART_INF_F;
            if (c + 2 == ry) v.z = -CUDART_INF_F;
            if (c + 3 == ry) v.w = -CUDART_INF_F;
            mm = fmaxf(mm, max4(v));
        }
#pragma unroll
        for (int o = 16; o; o >>= 1) mm = fmaxf(mm, __shfl_xor_sync(FULLM, mm, o));
        if (lane == l) neg = mm;          // exact masked max for this row
    }
    g_neg[i]  = sigmoidf_(neg);
    g_posm[i] = (yq != 0) ? (sigmoidf_(px) - GAMA) : CUDART_INF_F;
}

// ---------------- K2: hist + scan + scatter + suffix + queries (all smem, warp scans) ----------------
// smem layout (bytes from base):
//   [0      , 65544 )  double sS1[8193]   (overlay: float sraw[8192] @0,
//   [65544  , 131088)  double sS2[8193]    int shist[4096] @32768, int scursor[4096] @49152)
//   [131088 , 163856)  float  ssorted[8192]
//   [163856 , 180248)  int    sbinStart[4097] (+pad)
//   [180248 , 188440)  double p1[1024]
//   [188440 , 196632)  double p2[1024]
//   [196632 , 200728)  int    iscan[1024]
#define K2_SMEM 200728

__global__ __launch_bounds__(1024, 1) void k_main(float* __restrict__ out) {
    extern __shared__ unsigned char sm[];
    double* sS1      = (double*)(sm);
    double* sS2      = (double*)(sm + 65544);
    float*  ssorted  = (float*) (sm + 131088);
    int*    sbinStart= (int*)   (sm + 163856);
    double* p1       = (double*)(sm + 180248);
    double* p2       = (double*)(sm + 188440);
    int*    iscan    = (int*)   (sm + 196632);
    float*  sraw     = (float*) (sm);           // overlay, dead before sS1 written
    int*    shist    = (int*)   (sm + 32768);   // overlay
    int*    scursor  = (int*)   (sm + 49152);   // overlay

    const int tid  = threadIdx.x;
    const int lane = tid & 31;
    const int wid  = tid >> 5;

    // ---- phase 1: contiguous loads; neg -> smem, m -> regs ----
    float pm[8];
#pragma unroll
    for (int k = 0; k < 8; k++) {
        int i = tid + k * 1024;
        sraw[i] = g_neg[i];
        pm[k]   = g_posm[i];
    }
    for (int i = tid; i < NBINS; i += 1024) shist[i] = 0;
    __syncthreads();

    // ---- phase 2: histogram (warp-aggregated atomics) ----
#pragma unroll
    for (int k = 0; k < 8; k++) {
        int b = binOf(sraw[tid + k * 1024]);
        unsigned mask = __match_any_sync(FULLM, b);
        if (lane == (__ffs(mask) - 1)) atomicAdd(&shist[b], __popc(mask));
    }
    __syncthreads();

    // ---- phase 3: exclusive scan over 4096 bins (warp-shuffle scan) ----
    const int tb = tid * 4;
    int h0 = shist[tb], h1 = shist[tb + 1], h2 = shist[tb + 2], h3 = shist[tb + 3];
    int tsum = h0 + h1 + h2 + h3;
    int v = tsum;
#pragma unroll
    for (int o = 1; o < 32; o <<= 1) {
        int t = __shfl_up_sync(FULLM, v, o);
        if (lane >= o) v += t;
    }
    if (lane == 31) iscan[wid] = v;             // warp totals
    __syncthreads();
    if (wid == 0) {
        int w = iscan[lane];
        int s = w;
#pragma unroll
        for (int o = 1; o < 32; o <<= 1) {
            int t = __shfl_up_sync(FULLM, s, o);
            if (lane >= o) s += t;
        }
        iscan[32 + lane] = s - w;               // exclusive warp offsets
    }
    __syncthreads();
    {
        int ex = v + iscan[32 + wid] - tsum;    // exclusive prefix for this thread
        sbinStart[tb] = ex;     scursor[tb]     = ex; ex += h0;
        sbinStart[tb + 1] = ex; scursor[tb + 1] = ex; ex += h1;
        sbinStart[tb + 2] = ex; scursor[tb + 2] = ex; ex += h2;
        sbinStart[tb + 3] = ex; scursor[tb + 3] = ex; ex += h3;
        if (tid == 1023) sbinStart[NBINS] = ex; // = BB
    }
    __syncthreads();

    // ---- phase 4: scatter into bin-grouped order (warp-aggregated) ----
#pragma unroll
    for (int k = 0; k < 8; k++) {
        float val = sraw[tid + k * 1024];
        int b = binOf(val);
        unsigned mask = __match_any_sync(FULLM, b);
        int leader = __ffs(mask) - 1;
        int pos0 = 0;
        if (lane == leader) pos0 = atomicAdd(&scursor[b], __popc(mask));
        pos0 = __shfl_sync(FULLM, pos0, leader);
        ssorted[pos0 + __popc(mask & ((1u << lane) - 1u))] = val;
    }
    __syncthreads();   // sraw/shist/scursor dead from here

    // ---- phase 5: element-level suffix sums (double), warp-shuffle suffix scan ----
    const int base8 = tid * 8;
    double tl1[8], tl2[8];
    double a1 = 0.0, a2 = 0.0;
#pragma unroll
    for (int k = 7; k >= 0; --k) {
        float n = ssorted[base8 + k];
        a1 += (double)n;
        a2 += (double)n * (double)n;
        tl1[k] = a1; tl2[k] = a2;
    }
    double s1 = a1, s2 = a2;
#pragma unroll
    for (int o = 1; o < 32; o <<= 1) {
        double t1 = __shfl_down_sync(FULLM, s1, o);
        double t2 = __shfl_down_sync(FULLM, s2, o);
        if (lane + o < 32) { s1 += t1; s2 += t2; }
    }
    if (lane == 0) { p1[wid] = s1; p2[wid] = s2; }  // warp totals
    __syncthreads();
    if (wid == 0) {
        double w1 = p1[lane], w2 = p2[lane];
        double e1 = w1, e2 = w2;
#pragma unroll
        for (int o = 1; o < 32; o <<= 1) {
            double t1 = __shfl_down_sync(FULLM, e1, o);
            double t2 = __shfl_down_sync(FULLM, e2, o);
            if (lane + o < 32) { e1 += t1; e2 += t2; }
        }
        p1[32 + lane] = e1 - w1;               // exclusive suffix of higher warps
        p2[32 + lane] = e2 - w2;
    }
    __syncthreads();
    {
        double o1 = s1 + p1[32 + wid] - a1;    // sum strictly after this thread's chunk
        double o2 = s2 + p2[32 + wid] - a2;
#pragma unroll
        for (int k = 0; k < 8; k++) {
            sS1[base8 + k] = tl1[k] + o1;
            sS2[base8 + k] = tl2[k] + o2;
        }
        if (tid == 0) { sS1[BB] = 0.0; sS2[BB] = 0.0; }
    }
    __syncthreads();

    // ---- phase 6: queries + warp reduction ----
    double acc = 0.0;
    int vc = 0;
#pragma unroll
    for (int k = 0; k < 8; k++) {
        float m = pm[k];
        if (!(m < 1.0f)) continue;       // invalid (+INF)
        vc++;
        long long cnt; double S1, S2;
        if (m <= 0.0f) {
            cnt = BB; S1 = sS1[0]; S2 = sS2[0];
        } else {
            int b = binOf(m); if (b > NBINS - 1) b = NBINS - 1;
            int st = sbinStart[b], en = sbinStart[b + 1];
            cnt = BB - en; S1 = sS1[en]; S2 = sS2[en];
            for (int t = st; t < en; t++) {          // exact boundary-bin scan
                float n = ssorted[t];
                if (n > m) { cnt++; S1 += (double)n; S2 += (double)n * (double)n; }
            }
        }
        double md = (double)m;
        acc += (double)cnt * md * md - 2.0 * md * S1 + S2;
    }
#pragma unroll
    for (int o = 16; o; o >>= 1) {
        acc += __shfl_down_sync(FULLM, acc, o);
        vc  += __shfl_down_sync(FULLM, vc,  o);
    }
    if (lane == 0) { p1[wid] = acc; iscan[wid] = vc; }
    __syncthreads();
    if (tid == 0) {
        double s = 0.0; int c = 0;
#pragma unroll
        for (int w = 0; w < 32; w++) { s += p1[w]; c += iscan[w]; }
        out[0] = (float)(s / ((double)c + 1.0) / ((double)BB + 1.0));
    }
}

// ---------------- launch ----------------
extern "C" void kernel_launch(void* const* d_in, const int* in_sizes, int n_in,
                              void* d_out, int out_size) {
    const float* x = (const float*)d_in[0];
    const int*   y = (const int*)d_in[1];

    k_row<<<BB / 2 + 1, 128>>>(x, y);
    k_pos<<<64, 128>>>(x, y);
    cudaFuncSetAttribute(k_main, cudaFuncAttributeMaxDynamicSharedMemorySize, K2_SMEM);
    k_main<<<1, 1024, K2_SMEM>>>((float*)d_out);
}

// round 14
// speedup vs baseline: 1.0908x; 1.0085x over previous
#include <cuda_runtime.h>
#include <math_constants.h>
#include <cstdint>

#define BB 8192
#define CC 2048
#define NBINS 4096
#define GAMA 0.3f
#define FULLM 0xffffffffu

// ---------------- scratch (static __device__, no allocs) ----------------
__device__ float g_rowmax[BB]; // max over cols [1,C)
__device__ float g_neg[BB];    // sigmoid(max excluding label col and col 0)
__device__ float g_posm[BB];   // m_i = sigmoid(x[i,y])-gamma, +INF invalid
__device__ int   g_notI64;     // 1 = labels int32, 0 = int64

__device__ __forceinline__ float sigmoidf_(float v) { return 1.0f / (1.0f + __expf(-v)); }
// Monotonic bin for v in (0,1): positive-float bits are order-preserving.
__device__ __forceinline__ int binOf(float v) { return (int)(__float_as_uint(v) >> 19); }

__device__ __forceinline__ float max4(float4 v) {
    return fmaxf(fmaxf(v.x, v.y), fmaxf(v.z, v.w));
}

// 4 packed vector loads in ONE asm statement: all 16 results live simultaneously,
// no arithmetic can be scheduled between them -> consecutive LDG.128 in SASS.
#define LDG128x4(d0, d1, d2, d3, p0, p1, p2, p3)                                 \
    asm volatile(                                                                \
        "ld.global.nc.v4.f32 {%0,%1,%2,%3},     [%16];\n\t"                      \
        "ld.global.nc.v4.f32 {%4,%5,%6,%7},     [%17];\n\t"                      \
        "ld.global.nc.v4.f32 {%8,%9,%10,%11},   [%18];\n\t"                      \
        "ld.global.nc.v4.f32 {%12,%13,%14,%15}, [%19];"                          \
        : "=f"(d0.x), "=f"(d0.y), "=f"(d0.z), "=f"(d0.w),                        \
          "=f"(d1.x), "=f"(d1.y), "=f"(d1.z), "=f"(d1.w),                        \
          "=f"(d2.x), "=f"(d2.y), "=f"(d2.z), "=f"(d2.w),                        \
          "=f"(d3.x), "=f"(d3.y), "=f"(d3.z), "=f"(d3.w)                         \
        : "l"(p0), "l"(p1), "l"(p2), "l"(p3))

// ---------------- K1: two rows per 128-thread block; 8 forced-batch LDG.128/thread ----------------
__global__ __launch_bounds__(128) void k_row(const float* __restrict__ x,
                                             const int* __restrict__ wy) {
    const int tid  = threadIdx.x;
    const int lane = tid & 31;

    if (blockIdx.x == BB / 2) {
        // dedicated dtype-detect block: reads only words [0, BB) — safe for both dtypes.
        // int64 labels (<2048) -> odd words are zero high halves.
        int f = 0;
        for (int i = tid; i < BB / 2; i += 128) f |= wy[2 * i + 1];
#pragma unroll
        for (int o = 16; o; o >>= 1) f |= __shfl_xor_sync(FULLM, f, o);
        __shared__ int sf[4];
        if (lane == 0) sf[tid >> 5] = f;
        __syncthreads();
        if (tid == 0) g_notI64 = ((sf[0] | sf[1] | sf[2] | sf[3]) != 0);
        return;
    }

    const int row0 = blockIdx.x * 2;
    const float4* xa = (const float4*)(x + (size_t)row0 * CC);
    const float4* xb = (const float4*)(x + (size_t)(row0 + 1) * CC);

    float4 a0, a1, a2, a3, b0, b1, b2, b3;
    LDG128x4(a0, a1, a2, a3, xa + tid, xa + tid + 128, xa + tid + 256, xa + tid + 384);
    LDG128x4(b0, b1, b2, b3, xb + tid, xb + tid + 128, xb + tid + 256, xb + tid + 384);

    if (tid == 0) { a0.x = -CUDART_INF_F; b0.x = -CUDART_INF_F; }  // exclude col 0

    float ma = fmaxf(fmaxf(max4(a0), max4(a1)), fmaxf(max4(a2), max4(a3)));
    float mb = fmaxf(fmaxf(max4(b0), max4(b1)), fmaxf(max4(b2), max4(b3)));
#pragma unroll
    for (int o = 16; o; o >>= 1) {
        ma = fmaxf(ma, __shfl_xor_sync(FULLM, ma, o));
        mb = fmaxf(mb, __shfl_xor_sync(FULLM, mb, o));
    }
    __shared__ float wa[4], wb[4];
    if (lane == 0) { int w = tid >> 5; wa[w] = ma; wb[w] = mb; }
    __syncthreads();
    if (tid == 0) {
        float ra = fmaxf(fmaxf(wa[0], wa[1]), fmaxf(wa[2], wa[3]));
        float rb = fmaxf(fmaxf(wb[0], wb[1]), fmaxf(wb[2], wb[3]));
        *(float2*)&g_rowmax[row0] = make_float2(ra, rb);   // row0 even -> 8B aligned
    }
}

// ---------------- K1b: label select + pos gather; rare cooperative rescan ----------------
__global__ __launch_bounds__(128) void k_pos(const float* __restrict__ x,
                                             const int* __restrict__ wy) {
    const int i    = blockIdx.x * 128 + threadIdx.x;   // 64*128 = 8192
    const int lane = threadIdx.x & 31;
    const int notI64 = g_notI64;
    // wy[2*i] only dereferenced when labels proven int64 (buffer has 2*BB words)
    int yq = notI64 ? wy[i] : wy[2 * i];
    float m1 = g_rowmax[i];
    float px = __ldg(&x[(size_t)i * CC + yq]);

    float neg = m1;                       // correct unless label col holds the max
    bool need = (yq != 0) && (px == m1);  // exact: px is an element, m1 the exact max
    unsigned bal = __ballot_sync(FULLM, need);
    while (bal) {                         // ~4 rows expected across the whole grid
        int l  = __ffs(bal) - 1; bal &= bal - 1;
        int ri = __shfl_sync(FULLM, i,  l);
        int ry = __shfl_sync(FULLM, yq, l);
        const float4* xr = (const float4*)(x + (size_t)ri * CC);
        float mm = -CUDART_INF_F;
        for (int c4 = lane; c4 < CC / 4; c4 += 32) {
            float4 v = __ldg(xr + c4);
            int c = c4 * 4;
            if (c == 0)      v.x = -CUDART_INF_F;
            if (c + 0 == ry) v.x = -CUDART_INF_F;
            if (c + 1 == ry) v.y = -CUDART_INF_F;
            if (c + 2 == ry) v.z = -CUDART_INF_F;
            if (c + 3 == ry) v.w = -CUDART_INF_F;
            mm = fmaxf(mm, max4(v));
        }
#pragma unroll
        for (int o = 16; o; o >>= 1) mm = fmaxf(mm, __shfl_xor_sync(FULLM, mm, o));
        if (lane == l) neg = mm;          // exact masked max for this row
    }
    g_neg[i]  = sigmoidf_(neg);
    g_posm[i] = (yq != 0) ? (sigmoidf_(px) - GAMA) : CUDART_INF_F;
}

// ---------------- K2: hist + scan + scatter + suffix + queries (all smem, warp scans) ----------------
// smem layout (bytes from base):
//   [0      , 65544 )  double sS1[8193]   (overlay: float sraw[8192] @0,
//   [65544  , 131088)  double sS2[8193]    int shist[4096] @32768, int scursor[4096] @49152)
//   [131088 , 163856)  float  ssorted[8192]
//   [163856 , 180248)  int    sbinStart[4097] (+pad)
//   [180248 , 188440)  double p1[1024]
//   [188440 , 196632)  double p2[1024]
//   [196632 , 200728)  int    iscan[1024]
#define K2_SMEM 200728

__global__ __launch_bounds__(1024, 1) void k_main(float* __restrict__ out) {
    extern __shared__ unsigned char sm[];
    double* sS1      = (double*)(sm);
    double* sS2      = (double*)(sm + 65544);
    float*  ssorted  = (float*) (sm + 131088);
    int*    sbinStart= (int*)   (sm + 163856);
    double* p1       = (double*)(sm + 180248);
    double* p2       = (double*)(sm + 188440);
    int*    iscan    = (int*)   (sm + 196632);
    float*  sraw     = (float*) (sm);           // overlay, dead before sS1 written
    int*    shist    = (int*)   (sm + 32768);   // overlay
    int*    scursor  = (int*)   (sm + 49152);   // overlay

    const int tid  = threadIdx.x;
    const int lane = tid & 31;
    const int wid  = tid >> 5;

    // ---- phase 1: contiguous loads; neg -> smem, m -> regs ----
    float pm[8];
#pragma unroll
    for (int k = 0; k < 8; k++) {
        int i = tid + k * 1024;
        sraw[i] = g_neg[i];
        pm[k]   = g_posm[i];
    }
    for (int i = tid; i < NBINS; i += 1024) shist[i] = 0;
    __syncthreads();

    // ---- phase 2: histogram (warp-aggregated atomics) ----
#pragma unroll
    for (int k = 0; k < 8; k++) {
        int b = binOf(sraw[tid + k * 1024]);
        unsigned mask = __match_any_sync(FULLM, b);
        if (lane == (__ffs(mask) - 1)) atomicAdd(&shist[b], __popc(mask));
    }
    __syncthreads();

    // ---- phase 3: exclusive scan over 4096 bins (warp-shuffle scan) ----
    const int tb = tid * 4;
    int h0 = shist[tb], h1 = shist[tb + 1], h2 = shist[tb + 2], h3 = shist[tb + 3];
    int tsum = h0 + h1 + h2 + h3;
    int v = tsum;
#pragma unroll
    for (int o = 1; o < 32; o <<= 1) {
        int t = __shfl_up_sync(FULLM, v, o);
        if (lane >= o) v += t;
    }
    if (lane == 31) iscan[wid] = v;             // warp totals
    __syncthreads();
    if (wid == 0) {
        int w = iscan[lane];
        int s = w;
#pragma unroll
        for (int o = 1; o < 32; o <<= 1) {
            int t = __shfl_up_sync(FULLM, s, o);
            if (lane >= o) s += t;
        }
        iscan[32 + lane] = s - w;               // exclusive warp offsets
    }
    __syncthreads();
    {
        int ex = v + iscan[32 + wid] - tsum;    // exclusive prefix for this thread
        sbinStart[tb] = ex;     scursor[tb]     = ex; ex += h0;
        sbinStart[tb + 1] = ex; scursor[tb + 1] = ex; ex += h1;
        sbinStart[tb + 2] = ex; scursor[tb + 2] = ex; ex += h2;
        sbinStart[tb + 3] = ex; scursor[tb + 3] = ex; ex += h3;
        if (tid == 1023) sbinStart[NBINS] = ex; // = BB
    }
    __syncthreads();

    // ---- phase 4: scatter into bin-grouped order (warp-aggregated) ----
#pragma unroll
    for (int k = 0; k < 8; k++) {
        float val = sraw[tid + k * 1024];
        int b = binOf(val);
        unsigned mask = __match_any_sync(FULLM, b);
        int leader = __ffs(mask) - 1;
        int pos0 = 0;
        if (lane == leader) pos0 = atomicAdd(&scursor[b], __popc(mask));
        pos0 = __shfl_sync(FULLM, pos0, leader);
        ssorted[pos0 + __popc(mask & ((1u << lane) - 1u))] = val;
    }
    __syncthreads();   // sraw/shist/scursor dead from here

    // ---- phase 5: element-level suffix sums (double), warp-shuffle suffix scan ----
    const int base8 = tid * 8;
    double tl1[8], tl2[8];
    double a1 = 0.0, a2 = 0.0;
#pragma unroll
    for (int k = 7; k >= 0; --k) {
        float n = ssorted[base8 + k];
        a1 += (double)n;
        a2 += (double)n * (double)n;
        tl1[k] = a1; tl2[k] = a2;
    }
    double s1 = a1, s2 = a2;
#pragma unroll
    for (int o = 1; o < 32; o <<= 1) {
        double t1 = __shfl_down_sync(FULLM, s1, o);
        double t2 = __shfl_down_sync(FULLM, s2, o);
        if (lane + o < 32) { s1 += t1; s2 += t2; }
    }
    if (lane == 0) { p1[wid] = s1; p2[wid] = s2; }  // warp totals
    __syncthreads();
    if (wid == 0) {
        double w1 = p1[lane], w2 = p2[lane];
        double e1 = w1, e2 = w2;
#pragma unroll
        for (int o = 1; o < 32; o <<= 1) {
            double t1 = __shfl_down_sync(FULLM, e1, o);
            double t2 = __shfl_down_sync(FULLM, e2, o);
            if (lane + o < 32) { e1 += t1; e2 += t2; }
        }
        p1[32 + lane] = e1 - w1;               // exclusive suffix of higher warps
        p2[32 + lane] = e2 - w2;
    }
    __syncthreads();
    {
        double o1 = s1 + p1[32 + wid] - a1;    // sum strictly after this thread's chunk
        double o2 = s2 + p2[32 + wid] - a2;
#pragma unroll
        for (int k = 0; k < 8; k++) {
            sS1[base8 + k] = tl1[k] + o1;
            sS2[base8 + k] = tl2[k] + o2;
        }
        if (tid == 0) { sS1[BB] = 0.0; sS2[BB] = 0.0; }
    }
    __syncthreads();

    // ---- phase 6: queries + warp reduction ----
    double acc = 0.0;
    int vc = 0;
#pragma unroll
    for (int k = 0; k < 8; k++) {
        float m = pm[k];
        if (!(m < 1.0f)) continue;       // invalid (+INF)
        vc++;
        long long cnt; double S1, S2;
        if (m <= 0.0f) {
            cnt = BB; S1 = sS1[0]; S2 = sS2[0];
        } else {
            int b = binOf(m); if (b > NBINS - 1) b = NBINS - 1;
            int st = sbinStart[b], en = sbinStart[b + 1];
            cnt = BB - en; S1 = sS1[en]; S2 = sS2[en];
            for (int t = st; t < en; t++) {          // exact boundary-bin scan
                float n = ssorted[t];
                if (n > m) { cnt++; S1 += (double)n; S2 += (double)n * (double)n; }
            }
        }
        double md = (double)m;
        acc += (double)cnt * md * md - 2.0 * md * S1 + S2;
    }
#pragma unroll
    for (int o = 16; o; o >>= 1) {
        acc += __shfl_down_sync(FULLM, acc, o);
        vc  += __shfl_down_sync(FULLM, vc,  o);
    }
    if (lane == 0) { p1[wid] = acc; iscan[wid] = vc; }
    __syncthreads();
    if (tid == 0) {
        double s = 0.0; int c = 0;
#pragma unroll
        for (int w = 0; w < 32; w++) { s += p1[w]; c += iscan[w]; }
        out[0] = (float)(s / ((double)c + 1.0) / ((double)BB + 1.0));
    }
}

// ---------------- launch ----------------
extern "C" void kernel_launch(void* const* d_in, const int* in_sizes, int n_in,
                              void* d_out, int out_size) {
    const float* x = (const float*)d_in[0];
    const int*   y = (const int*)d_in[1];

    k_row<<<BB / 2 + 1, 128>>>(x, y);
    k_pos<<<64, 128>>>(x, y);
    cudaFuncSetAttribute(k_main, cudaFuncAttributeMaxDynamicSharedMemorySize, K2_SMEM);
    k_main<<<1, 1024, K2_SMEM>>>((float*)d_out);
}